// round 16
// baseline (speedup 1.0000x reference)
#include <cuda_runtime.h>
#include <cuda_fp16.h>
#include <cstdint>
#include <math.h>

#define T_TOK  4096
#define HID    2048
#define INTERD 10944
#define EPS    1e-6f

#define BK 64            // 64 halves = 128 bytes per row
#define STAGES 4
#define STAGE_B  49152
#define SMEM_TOTAL (STAGES * STAGE_B)  // 196608

#define NTHREADS 512
#define NKTOT_DOWN (INTERD / BK)   // 171
#define NK_CHUNK   43              // 43+43+43+42

// ---------------- scratch (device globals; allocation-free rule) ----------------
__device__ __half g_hnorm [(size_t)T_TOK * HID];
__device__ float  g_hidden[(size_t)T_TOK * HID];
__device__ __half g_hpost [(size_t)T_TOK * HID];
__device__ __half g_act   [(size_t)T_TOK * INTERD];
__device__ __half g_part  [(size_t)4 * T_TOK * HID];   // split-K fp16 partials (down proj)
__device__ __half g_hWqT  [(size_t)HID * HID];   // fp16(Wq)^T  [h_in, q]
__device__ __half g_hWo   [(size_t)HID * HID];
__device__ __half g_hWqo  [(size_t)HID * HID];   // fp16(Wo @ Wq) [h_out, h_in]
__device__ __half g_hWg   [(size_t)INTERD * HID];
__device__ __half g_hWu   [(size_t)INTERD * HID];
__device__ __half g_hWd   [(size_t)HID * INTERD];

// ---------------- PTX helpers ----------------
static __device__ __forceinline__ uint32_t s2u(const void* p) {
    uint32_t a;
    asm("{ .reg .u64 t; cvta.to.shared.u64 t, %1; cvt.u32.u64 %0, t; }" : "=r"(a) : "l"(p));
    return a;
}
static __device__ __forceinline__ void cpa16(uint32_t s, const void* g) {
    asm volatile("cp.async.cg.shared.global [%0], [%1], 16;" :: "r"(s), "l"(g));
}
static __device__ __forceinline__ void ldsm4(uint32_t& r0, uint32_t& r1,
                                             uint32_t& r2, uint32_t& r3, uint32_t addr) {
    asm volatile("ldmatrix.sync.aligned.m8n8.x4.shared.b16 {%0,%1,%2,%3}, [%4];"
                 : "=r"(r0), "=r"(r1), "=r"(r2), "=r"(r3) : "r"(addr));
}
static __device__ __forceinline__ void mma_f16(float* c, const uint32_t* a,
                                               uint32_t b0, uint32_t b1) {
    asm volatile(
        "mma.sync.aligned.m16n8k16.row.col.f32.f16.f16.f32 "
        "{%0,%1,%2,%3}, {%4,%5,%6,%7}, {%8,%9}, {%0,%1,%2,%3};"
        : "+f"(c[0]), "+f"(c[1]), "+f"(c[2]), "+f"(c[3])
        : "r"(a[0]), "r"(a[1]), "r"(a[2]), "r"(a[3]), "r"(b0), "r"(b1));
}
static __device__ __forceinline__ uint32_t sw128(uint32_t off) {
    return off ^ ((off >> 3) & 0x70);
}
// fast silu via explicit intrinsics: 1 EX2 + 1 RCP
static __device__ __forceinline__ float fsilu(float g) {
    return __fdividef(g, 1.f + __expf(-g));
}

// ---------------- RMSNorm (fp32 in, fp16-RNE out) ----------------
__global__ __launch_bounds__(256) void rmsnorm_kernel(
    const float* __restrict__ x, const float* __restrict__ w, __half* __restrict__ out)
{
    long row = blockIdx.x;
    const float4* xr = (const float4*)(x + row * (long)HID);
    const float4* wr = (const float4*)w;
    __half2* orow = (__half2*)(out + row * (long)HID);
    int tid = threadIdx.x;

    float4 v0 = xr[tid];
    float4 v1 = xr[tid + 256];
    float ss = v0.x*v0.x + v0.y*v0.y + v0.z*v0.z + v0.w*v0.w
             + v1.x*v1.x + v1.y*v1.y + v1.z*v1.z + v1.w*v1.w;

    #pragma unroll
    for (int off = 16; off > 0; off >>= 1)
        ss += __shfl_xor_sync(0xffffffffu, ss, off);

    __shared__ float warp_ss[8];
    __shared__ float s_scale;
    int lane = tid & 31, wid = tid >> 5;
    if (lane == 0) warp_ss[wid] = ss;
    __syncthreads();
    if (tid == 0) {
        float tot = 0.f;
        #pragma unroll
        for (int i = 0; i < 8; i++) tot += warp_ss[i];
        s_scale = rsqrtf(tot / (float)HID + EPS);
    }
    __syncthreads();
    float scale = s_scale;

    float4 w0 = wr[tid];
    float4 w1 = wr[tid + 256];
    orow[2*tid]       = __floats2half2_rn(v0.x * scale * w0.x, v0.y * scale * w0.y);
    orow[2*tid + 1]   = __floats2half2_rn(v0.z * scale * w0.z, v0.w * scale * w0.w);
    orow[2*tid + 512] = __floats2half2_rn(v1.x * scale * w1.x, v1.y * scale * w1.y);
    orow[2*tid + 513] = __floats2half2_rn(v1.z * scale * w1.z, v1.w * scale * w1.w);
}

// ---------------- fp32 -> fp16(RNE) elementwise ----------------
__global__ __launch_bounds__(256) void to_f16_kernel(
    const float4* __restrict__ s, uint2* __restrict__ d, long n4)
{
    long i = (long)blockIdx.x * blockDim.x + threadIdx.x;
    long stride = (long)gridDim.x * blockDim.x;
    for (; i < n4; i += stride) {
        float4 v = s[i];
        __half2 lo = __floats2half2_rn(v.x, v.y);
        __half2 hi = __floats2half2_rn(v.z, v.w);
        uint2 o;
        o.x = *(uint32_t*)&lo;
        o.y = *(uint32_t*)&hi;
        d[i] = o;
    }
}

// ---------------- Wqo prep: Wq -> fp16 transposed, Wo -> fp16, one kernel ----------------
__global__ __launch_bounds__(256) void prep_wqo_kernel(
    const float* __restrict__ Wq, const float* __restrict__ Wo,
    __half* __restrict__ WqT, __half* __restrict__ WoH)
{
    __shared__ float tile[32][33];
    int x = blockIdx.x * 32 + threadIdx.x;   // src col
    int y0 = blockIdx.y * 32 + threadIdx.y;  // src row
    #pragma unroll
    for (int i = 0; i < 32; i += 8) {
        size_t idx = (size_t)(y0 + i) * HID + x;
        tile[threadIdx.y + i][threadIdx.x] = Wq[idx];
        WoH[idx] = __float2half_rn(Wo[idx]);   // straight convert, coalesced
    }
    __syncthreads();
    int tx = blockIdx.y * 32 + threadIdx.x;  // dst col (= src row)
    int ty = blockIdx.x * 32 + threadIdx.y;  // dst row (= src col)
    #pragma unroll
    for (int i = 0; i < 32; i += 8)
        WqT[(size_t)(ty + i) * HID + tx] = __float2half_rn(tile[threadIdx.x][threadIdx.y + i]);
}

// ---------------- combine: out = hidden + p0 + p1 + p2 + p3  (fp16 partials) ----------------
__global__ __launch_bounds__(256) void combine_kernel(
    const float4* __restrict__ h, const uint2* __restrict__ p,
    float4* __restrict__ o, long n4)
{
    long i = (long)blockIdx.x * blockDim.x + threadIdx.x;
    long stride = (long)gridDim.x * blockDim.x;
    for (; i < n4; i += stride) {
        float4 a = h[i];
        #pragma unroll
        for (int z = 0; z < 4; z++) {
            uint2 pv = p[i + (long)z * n4];
            __half2 lo = *(__half2*)&pv.x;
            __half2 hi = *(__half2*)&pv.y;
            float2 flo = __half22float2(lo);
            float2 fhi = __half22float2(hi);
            a.x += flo.x; a.y += flo.y;
            a.z += fhi.x; a.w += fhi.y;
        }
        o[i] = a;
    }
}

// ---------------- plain GEMM: C[M,N] = A @ W^T (+R), mma.sync fp16 ----------------
// CTA tile 128x256, BK=64, 4-slot/3-inflight cp.async, single sync per iter,
// 16 warps (4M x 4N), warp tile 32x64, kk-level fragment double buffering.
// EPI 0: C(half) = rn(A@W^T);  EPI 1: C(float) = R + A@W^T
template<int EPI>
__global__ __launch_bounds__(NTHREADS, 1) void gemm_mma(
    const __half* __restrict__ A, const __half* __restrict__ W,
    const float* __restrict__ R, void* __restrict__ Cv, int K, int N)
{
    extern __shared__ __align__(1024) char smem[];
    uint32_t sb = s2u(smem);
    int tid = threadIdx.x;
    int lane = tid & 31, w = tid >> 5;
    int wm = w >> 2;      // 0..3  (32-row slice)
    int wn = w & 3;       // 0..3  (64-col slice)
    size_t row0 = (size_t)blockIdx.x * 128;
    size_t col0 = (size_t)blockIdx.y * 256;
    const int NK = K / BK;

    const __half* Abase = A + row0 * (size_t)K;
    const __half* Wbase = W + col0 * (size_t)K;

    auto load_stage = [&](int slot, int j) {
        uint32_t ab = sb + (uint32_t)slot * STAGE_B;
        uint32_t bb = ab + 16384;
        int kt = j * BK;
        #pragma unroll
        for (int p = 0; p < 2; p++) {
            int idx = p * NTHREADS + tid;
            int r = idx >> 3, c = idx & 7;   // 8 x 16B chunks per 128B row
            cpa16(ab + sw128((r << 7) + (c << 4)),
                  (const char*)(Abase + (size_t)r * K + kt) + (c << 4));
        }
        #pragma unroll
        for (int p = 0; p < 4; p++) {
            int idx = p * NTHREADS + tid;
            int r = idx >> 3, c = idx & 7;
            cpa16(bb + sw128((r << 7) + (c << 4)),
                  (const char*)(Wbase + (size_t)r * K + kt) + (c << 4));
        }
    };

    auto load_afr = [&](uint32_t ab, int kk, uint32_t af[2][4]) {
        #pragma unroll
        for (int mi = 0; mi < 2; mi++) {
            uint32_t off = (uint32_t)((wm * 32 + mi * 16 + (lane & 15)) << 7)
                         + (uint32_t)((kk << 5) + ((lane >> 4) << 4));
            ldsm4(af[mi][0], af[mi][1], af[mi][2], af[mi][3], ab + sw128(off));
        }
    };
    auto load_bfr = [&](uint32_t bb, int kk, uint32_t bf[8][2]) {
        #pragma unroll
        for (int bi = 0; bi < 4; bi++) {
            uint32_t off = (uint32_t)((wn * 64 + bi * 16 + ((lane >> 4) << 3) + (lane & 7)) << 7)
                         + (uint32_t)((kk << 5) + (((lane >> 3) & 1) << 4));
            ldsm4(bf[2*bi][0], bf[2*bi][1], bf[2*bi+1][0], bf[2*bi+1][1], bb + sw128(off));
        }
    };

    float acc[2][8][4];
    #pragma unroll
    for (int i = 0; i < 2; i++)
        #pragma unroll
        for (int jx = 0; jx < 8; jx++)
            #pragma unroll
            for (int e = 0; e < 4; e++) acc[i][jx][e] = 0.f;

    #pragma unroll
    for (int p = 0; p < STAGES - 1; p++) {
        load_stage(p, p);
        asm volatile("cp.async.commit_group;");
    }

    for (int j = 0; j < NK; j++) {
        asm volatile("cp.async.wait_group %0;" :: "n"(STAGES - 2));
        __syncthreads();
        if (j + STAGES - 1 < NK) load_stage((j + STAGES - 1) & 3, j + STAGES - 1);
        asm volatile("cp.async.commit_group;");

        int slot = j & 3;
        uint32_t ab = sb + (uint32_t)slot * STAGE_B;
        uint32_t bb = ab + 16384;

        uint32_t afr[2][2][4], bfr[2][8][2];
        load_afr(ab, 0, afr[0]);
        load_bfr(bb, 0, bfr[0]);
        #pragma unroll
        for (int kk = 0; kk < 4; kk++) {
            if (kk < 3) {
                load_afr(ab, kk + 1, afr[(kk + 1) & 1]);
                load_bfr(bb, kk + 1, bfr[(kk + 1) & 1]);
            }
            #pragma unroll
            for (int mi = 0; mi < 2; mi++)
                #pragma unroll
                for (int nj = 0; nj < 8; nj++)
                    mma_f16(acc[mi][nj], afr[kk & 1][mi], bfr[kk & 1][nj][0], bfr[kk & 1][nj][1]);
        }
        __syncthreads();
    }

    #pragma unroll
    for (int mi = 0; mi < 2; mi++) {
        size_t r = row0 + wm * 32 + mi * 16 + (lane >> 2);
        #pragma unroll
        for (int nj = 0; nj < 8; nj++) {
            size_t c = col0 + wn * 64 + nj * 8 + 2 * (lane & 3);
            if (EPI == 1) {
                float* C = (float*)Cv;
                const float2 r0 = *(const float2*)(R + r * (size_t)N + c);
                const float2 r1 = *(const float2*)(R + (r + 8) * (size_t)N + c);
                float2 v0 = make_float2(acc[mi][nj][0] + r0.x, acc[mi][nj][1] + r0.y);
                float2 v1 = make_float2(acc[mi][nj][2] + r1.x, acc[mi][nj][3] + r1.y);
                *(float2*)(C + r * (size_t)N + c) = v0;
                *(float2*)(C + (r + 8) * (size_t)N + c) = v1;
            } else {
                __half2* C = (__half2*)Cv;
                C[(r * (size_t)N + c) >> 1]       = __floats2half2_rn(acc[mi][nj][0], acc[mi][nj][1]);
                C[((r + 8) * (size_t)N + c) >> 1] = __floats2half2_rn(acc[mi][nj][2], acc[mi][nj][3]);
            }
        }
    }
}

// ---------------- down-proj split-K GEMM: P[z] = rn16(A[:, Kz] @ Wd[:, Kz]^T) ----------------
// Identical 128x256 mainloop; blockIdx.z selects K-chunk (43/43/43/42 BK-blocks).
// Writes fp16 partials; combine_kernel sums them (fp32) with the residual.
__global__ __launch_bounds__(NTHREADS, 1) void gemm_down_sk(
    const __half* __restrict__ A, const __half* __restrict__ W,
    __half* __restrict__ P, int K, int N)
{
    extern __shared__ __align__(1024) char smem[];
    uint32_t sb = s2u(smem);
    int tid = threadIdx.x;
    int lane = tid & 31, w = tid >> 5;
    int wm = w >> 2;
    int wn = w & 3;
    size_t row0 = (size_t)blockIdx.x * 128;
    size_t col0 = (size_t)blockIdx.y * 256;
    int z = blockIdx.z;
    int nk0 = z * NK_CHUNK;
    int NK = NKTOT_DOWN - nk0 < NK_CHUNK ? NKTOT_DOWN - nk0 : NK_CHUNK;

    const __half* Abase = A + row0 * (size_t)K + (size_t)nk0 * BK;
    const __half* Wbase = W + col0 * (size_t)K + (size_t)nk0 * BK;
    __half* Pz = P + (size_t)z * T_TOK * HID;

    auto load_stage = [&](int slot, int j) {
        uint32_t ab = sb + (uint32_t)slot * STAGE_B;
        uint32_t bb = ab + 16384;
        int kt = j * BK;
        #pragma unroll
        for (int p = 0; p < 2; p++) {
            int idx = p * NTHREADS + tid;
            int r = idx >> 3, c = idx & 7;
            cpa16(ab + sw128((r << 7) + (c << 4)),
                  (const char*)(Abase + (size_t)r * K + kt) + (c << 4));
        }
        #pragma unroll
        for (int p = 0; p < 4; p++) {
            int idx = p * NTHREADS + tid;
            int r = idx >> 3, c = idx & 7;
            cpa16(bb + sw128((r << 7) + (c << 4)),
                  (const char*)(Wbase + (size_t)r * K + kt) + (c << 4));
        }
    };

    auto load_afr = [&](uint32_t ab, int kk, uint32_t af[2][4]) {
        #pragma unroll
        for (int mi = 0; mi < 2; mi++) {
            uint32_t off = (uint32_t)((wm * 32 + mi * 16 + (lane & 15)) << 7)
                         + (uint32_t)((kk << 5) + ((lane >> 4) << 4));
            ldsm4(af[mi][0], af[mi][1], af[mi][2], af[mi][3], ab + sw128(off));
        }
    };
    auto load_bfr = [&](uint32_t bb, int kk, uint32_t bf[8][2]) {
        #pragma unroll
        for (int bi = 0; bi < 4; bi++) {
            uint32_t off = (uint32_t)((wn * 64 + bi * 16 + ((lane >> 4) << 3) + (lane & 7)) << 7)
                         + (uint32_t)((kk << 5) + (((lane >> 3) & 1) << 4));
            ldsm4(bf[2*bi][0], bf[2*bi][1], bf[2*bi+1][0], bf[2*bi+1][1], bb + sw128(off));
        }
    };

    float acc[2][8][4];
    #pragma unroll
    for (int i = 0; i < 2; i++)
        #pragma unroll
        for (int jx = 0; jx < 8; jx++)
            #pragma unroll
            for (int e = 0; e < 4; e++) acc[i][jx][e] = 0.f;

    #pragma unroll
    for (int p = 0; p < STAGES - 1; p++) {
        load_stage(p, p);
        asm volatile("cp.async.commit_group;");
    }

    for (int j = 0; j < NK; j++) {
        asm volatile("cp.async.wait_group %0;" :: "n"(STAGES - 2));
        __syncthreads();
        if (j + STAGES - 1 < NK) load_stage((j + STAGES - 1) & 3, j + STAGES - 1);
        asm volatile("cp.async.commit_group;");

        int slot = j & 3;
        uint32_t ab = sb + (uint32_t)slot * STAGE_B;
        uint32_t bb = ab + 16384;

        uint32_t afr[2][2][4], bfr[2][8][2];
        load_afr(ab, 0, afr[0]);
        load_bfr(bb, 0, bfr[0]);
        #pragma unroll
        for (int kk = 0; kk < 4; kk++) {
            if (kk < 3) {
                load_afr(ab, kk + 1, afr[(kk + 1) & 1]);
                load_bfr(bb, kk + 1, bfr[(kk + 1) & 1]);
            }
            #pragma unroll
            for (int mi = 0; mi < 2; mi++)
                #pragma unroll
                for (int nj = 0; nj < 8; nj++)
                    mma_f16(acc[mi][nj], afr[kk & 1][mi], bfr[kk & 1][nj][0], bfr[kk & 1][nj][1]);
        }
        __syncthreads();
    }

    #pragma unroll
    for (int mi = 0; mi < 2; mi++) {
        size_t r = row0 + wm * 32 + mi * 16 + (lane >> 2);
        #pragma unroll
        for (int nj = 0; nj < 8; nj++) {
            size_t c = col0 + wn * 64 + nj * 8 + 2 * (lane & 3);
            *(__half2*)(Pz + r * (size_t)N + c)       = __floats2half2_rn(acc[mi][nj][0], acc[mi][nj][1]);
            *(__half2*)(Pz + (r + 8) * (size_t)N + c) = __floats2half2_rn(acc[mi][nj][2], acc[mi][nj][3]);
        }
    }
}

// ---------------- fused gate/up GEMM: act(half) = rn(silu(A@Wg^T) * (A@Wu^T)) ----------------
__global__ __launch_bounds__(NTHREADS, 1) void gemm_gateup_mma(
    const __half* __restrict__ A, const __half* __restrict__ Wg,
    const __half* __restrict__ Wu, __half* __restrict__ C, int K, int N)
{
    extern __shared__ __align__(1024) char smem[];
    uint32_t sb = s2u(smem);
    int tid = threadIdx.x;
    int lane = tid & 31, w = tid >> 5;
    int wm = w >> 2;      // 0..3 (32-row slice)
    int wn = w & 3;       // 0..3 (32-col slice)
    size_t row0 = (size_t)blockIdx.x * 128;
    size_t col0 = (size_t)blockIdx.y * 128;
    const int NK = K / BK;

    const __half* Abase = A + row0 * (size_t)K;
    const __half* Gbase = Wg + col0 * (size_t)K;
    const __half* Ubase = Wu + col0 * (size_t)K;
    int nvalid = (int)((size_t)N - col0 < 128 ? (size_t)N - col0 : 128);

    auto load_stage = [&](int slot, int j) {
        uint32_t ab = sb + (uint32_t)slot * STAGE_B;
        uint32_t gb = ab + 16384;
        uint32_t ub = gb + 16384;
        int kt = j * BK;
        #pragma unroll
        for (int p = 0; p < 2; p++) {
            int idx = p * NTHREADS + tid;
            int r = idx >> 3, c = idx & 7;
            cpa16(ab + sw128((r << 7) + (c << 4)),
                  (const char*)(Abase + (size_t)r * K + kt) + (c << 4));
        }
        #pragma unroll
        for (int p = 0; p < 2; p++) {
            int idx = p * NTHREADS + tid;
            int r = idx >> 3, c = idx & 7;
            if (r < nvalid) {
                uint32_t swo = sw128((r << 7) + (c << 4));
                cpa16(gb + swo, (const char*)(Gbase + (size_t)r * K + kt) + (c << 4));
                cpa16(ub + swo, (const char*)(Ubase + (size_t)r * K + kt) + (c << 4));
            }
        }
    };

    auto load_afr = [&](uint32_t ab, int kk, uint32_t af[2][4]) {
        #pragma unroll
        for (int mi = 0; mi < 2; mi++) {
            uint32_t off = (uint32_t)((wm * 32 + mi * 16 + (lane & 15)) << 7)
                         + (uint32_t)((kk << 5) + ((lane >> 4) << 4));
            ldsm4(af[mi][0], af[mi][1], af[mi][2], af[mi][3], ab + sw128(off));
        }
    };
    auto load_wfr = [&](uint32_t wb, int kk, uint32_t wf[4][2]) {
        #pragma unroll
        for (int bi = 0; bi < 2; bi++) {
            uint32_t off = (uint32_t)((wn * 32 + bi * 16 + ((lane >> 4) << 3) + (lane & 7)) << 7)
                         + (uint32_t)((kk << 5) + (((lane >> 3) & 1) << 4));
            ldsm4(wf[2*bi][0], wf[2*bi][1], wf[2*bi+1][0], wf[2*bi+1][1], wb + sw128(off));
        }
    };

    float accg[2][4][4], accu[2][4][4];
    #pragma unroll
    for (int i = 0; i < 2; i++)
        #pragma unroll
        for (int jx = 0; jx < 4; jx++)
            #pragma unroll
            for (int e = 0; e < 4; e++) { accg[i][jx][e] = 0.f; accu[i][jx][e] = 0.f; }

    #pragma unroll
    for (int p = 0; p < STAGES - 1; p++) {
        load_stage(p, p);
        asm volatile("cp.async.commit_group;");
    }

    for (int j = 0; j < NK; j++) {
        asm volatile("cp.async.wait_group %0;" :: "n"(STAGES - 2));
        __syncthreads();
        if (j + STAGES - 1 < NK) load_stage((j + STAGES - 1) & 3, j + STAGES - 1);
        asm volatile("cp.async.commit_group;");

        int slot = j & 3;
        uint32_t ab = sb + (uint32_t)slot * STAGE_B;
        uint32_t gb = ab + 16384;
        uint32_t ub = gb + 16384;

        uint32_t afr[2][2][4], gfr[2][4][2], ufr[2][4][2];
        load_afr(ab, 0, afr[0]);
        load_wfr(gb, 0, gfr[0]);
        load_wfr(ub, 0, ufr[0]);
        #pragma unroll
        for (int kk = 0; kk < 4; kk++) {
            if (kk < 3) {
                load_afr(ab, kk + 1, afr[(kk + 1) & 1]);
                load_wfr(gb, kk + 1, gfr[(kk + 1) & 1]);
                load_wfr(ub, kk + 1, ufr[(kk + 1) & 1]);
            }
            #pragma unroll
            for (int mi = 0; mi < 2; mi++)
                #pragma unroll
                for (int nj = 0; nj < 4; nj++) {
                    mma_f16(accg[mi][nj], afr[kk & 1][mi], gfr[kk & 1][nj][0], gfr[kk & 1][nj][1]);
                    mma_f16(accu[mi][nj], afr[kk & 1][mi], ufr[kk & 1][nj][0], ufr[kk & 1][nj][1]);
                }
        }
        __syncthreads();
    }

    #pragma unroll
    for (int mi = 0; mi < 2; mi++) {
        size_t r = row0 + wm * 32 + mi * 16 + (lane >> 2);
        #pragma unroll
        for (int nj = 0; nj < 4; nj++) {
            size_t c = col0 + wn * 32 + nj * 8 + 2 * (lane & 3);
            if (c < (size_t)N) {
                __half2 v0 = __floats2half2_rn(fsilu(accg[mi][nj][0]) * accu[mi][nj][0],
                                               fsilu(accg[mi][nj][1]) * accu[mi][nj][1]);
                __half2 v1 = __floats2half2_rn(fsilu(accg[mi][nj][2]) * accu[mi][nj][2],
                                               fsilu(accg[mi][nj][3]) * accu[mi][nj][3]);
                *(__half2*)(C + r * (size_t)N + c) = v0;
                *(__half2*)(C + (r + 8) * (size_t)N + c) = v1;
            }
        }
    }
}

// ---------------- launch ----------------
extern "C" void kernel_launch(void* const* d_in, const int* in_sizes, int n_in,
                              void* d_out, int out_size)
{
    const float* x      = (const float*)d_in[0];
    const float* in_w   = (const float*)d_in[2];
    const float* post_w = (const float*)d_in[3];
    const float* Wq     = (const float*)d_in[4];
    const float* Wo     = (const float*)d_in[5];
    const float* Wg     = (const float*)d_in[6];
    const float* Wu     = (const float*)d_in[7];
    const float* Wd     = (const float*)d_in[8];
    float* out = (float*)d_out;

    __half *hnorm, *hpost, *act, *part, *hWqT, *hWo, *hWqo, *hWg, *hWu, *hWd;
    float *hidden;
    cudaGetSymbolAddress((void**)&hnorm,  g_hnorm);
    cudaGetSymbolAddress((void**)&hidden, g_hidden);
    cudaGetSymbolAddress((void**)&hpost,  g_hpost);
    cudaGetSymbolAddress((void**)&act,    g_act);
    cudaGetSymbolAddress((void**)&part,   g_part);
    cudaGetSymbolAddress((void**)&hWqT,   g_hWqT);
    cudaGetSymbolAddress((void**)&hWo,    g_hWo);
    cudaGetSymbolAddress((void**)&hWqo,   g_hWqo);
    cudaGetSymbolAddress((void**)&hWg,    g_hWg);
    cudaGetSymbolAddress((void**)&hWu,    g_hWu);
    cudaGetSymbolAddress((void**)&hWd,    g_hWd);

    static cudaStream_t s2 = nullptr;
    static cudaEvent_t ev_fork = nullptr, ev_wqo = nullptr, ev_join = nullptr;
    if (s2 == nullptr) {
        cudaStreamCreateWithFlags(&s2, cudaStreamNonBlocking);
        cudaEventCreateWithFlags(&ev_fork, cudaEventDisableTiming);
        cudaEventCreateWithFlags(&ev_wqo,  cudaEventDisableTiming);
        cudaEventCreateWithFlags(&ev_join, cudaEventDisableTiming);
        cudaFuncSetAttribute(gemm_mma<0>, cudaFuncAttributeMaxDynamicSharedMemorySize, SMEM_TOTAL);
        cudaFuncSetAttribute(gemm_mma<1>, cudaFuncAttributeMaxDynamicSharedMemorySize, SMEM_TOTAL);
        cudaFuncSetAttribute(gemm_down_sk, cudaFuncAttributeMaxDynamicSharedMemorySize, SMEM_TOTAL);
        cudaFuncSetAttribute(gemm_gateup_mma, cudaFuncAttributeMaxDynamicSharedMemorySize, SMEM_TOTAL);
    }

    const int CB = 1184;

    // ---- fork: Wqo chain first on s2 (it heads the critical path), then big converts ----
    cudaEventRecord(ev_fork, 0);
    cudaStreamWaitEvent(s2, ev_fork, 0);
    // Wq -> fp16 transposed AND Wo -> fp16, single kernel
    prep_wqo_kernel<<<dim3(HID/32, HID/32), dim3(32, 8), 0, s2>>>(Wq, Wo, hWqT, hWo);
    // Wqo = rn16(Wo @ Wq):  C[i,j] = sum_q Wo[i,q] * WqT[j,q]
    gemm_mma<0><<<dim3(HID/128, HID/256), NTHREADS, SMEM_TOTAL, s2>>>(hWo, hWqT, nullptr, hWqo, HID, HID);
    cudaEventRecord(ev_wqo, s2);
    // big MLP weight converts (overlap the hidden GEMM on the main stream)
    to_f16_kernel<<<CB, 256, 0, s2>>>((const float4*)Wg, (uint2*)hWg, (long)INTERD * HID / 4);
    to_f16_kernel<<<CB, 256, 0, s2>>>((const float4*)Wu, (uint2*)hWu, (long)INTERD * HID / 4);
    to_f16_kernel<<<CB, 256, 0, s2>>>((const float4*)Wd, (uint2*)hWd, (long)HID * INTERD / 4);
    cudaEventRecord(ev_join, s2);

    // ---- main stream ----
    // 1. h_norm = rn(rmsnorm(x) * in_w)   (concurrent with the Wqo chain)
    rmsnorm_kernel<<<T_TOK, 256>>>(x, in_w, hnorm);
    cudaStreamWaitEvent(0, ev_wqo, 0);
    // 2+3 fused. hidden = x + h_norm @ Wqo^T
    gemm_mma<1><<<dim3(T_TOK/128, HID/256), NTHREADS, SMEM_TOTAL>>>(hnorm, hWqo, x, hidden, HID, HID);
    // 4. h_post = rn(rmsnorm(hidden) * post_w)
    rmsnorm_kernel<<<T_TOK, 256>>>(hidden, post_w, hpost);
    // join: MLP weight converts must be done
    cudaStreamWaitEvent(0, ev_join, 0);
    // 5. act = rn(silu(h_post @ Wg^T) * (h_post @ Wu^T))   [86 tiles, last ragged 64]
    gemm_gateup_mma<<<dim3(T_TOK/128, (INTERD + 127)/128), NTHREADS, SMEM_TOTAL>>>(hpost, hWg, hWu, act, HID, INTERD);
    // 6. split-K down: P[z] = rn16(act[:, Kz] @ Wd[:, Kz]^T)  (grid z = 4 chunks, 1024 CTAs)
    gemm_down_sk<<<dim3(T_TOK/128, HID/256, 4), NTHREADS, SMEM_TOTAL>>>(act, hWd, part, INTERD, HID);
    // 7. out = hidden + p0 + p1 + p2 + p3
    combine_kernel<<<CB, 256>>>((const float4*)hidden, (const uint2*)part, (float4*)out,
                                (long)T_TOK * HID / 4);
}

// round 17
// speedup vs baseline: 1.5125x; 1.5125x over previous
#include <cuda_runtime.h>
#include <cuda_fp16.h>
#include <cstdint>
#include <math.h>

#define T_TOK  4096
#define HID    2048
#define INTERD 10944
#define EPS    1e-6f

#define BK 64            // 64 halves = 128 bytes per row
#define STAGES 4
#define STAGE_B  49152
#define SMEM_TOTAL (STAGES * STAGE_B)  // 196608

#define NTHREADS 512
#define NKTOT_DOWN (INTERD / BK)   // 171
#define NK_CHUNK   43              // 43+43+43+42

// ---------------- scratch (device globals; allocation-free rule) ----------------
__device__ __half g_hnorm [(size_t)T_TOK * HID];
__device__ float  g_hidden[(size_t)T_TOK * HID];
__device__ __half g_hpost [(size_t)T_TOK * HID];
__device__ __half g_act   [(size_t)T_TOK * INTERD];
__device__ float  g_part  [(size_t)4 * T_TOK * HID];   // split-K partials (down proj)
__device__ __half g_hWqT  [(size_t)HID * HID];   // fp16(Wq)^T  [h_in, q]
__device__ __half g_hWo   [(size_t)HID * HID];
__device__ __half g_hWqo  [(size_t)HID * HID];   // fp16(Wo @ Wq) [h_out, h_in]
__device__ __half g_hWg   [(size_t)INTERD * HID];
__device__ __half g_hWu   [(size_t)INTERD * HID];
__device__ __half g_hWd   [(size_t)HID * INTERD];

// ---------------- PTX helpers ----------------
static __device__ __forceinline__ uint32_t s2u(const void* p) {
    uint32_t a;
    asm("{ .reg .u64 t; cvta.to.shared.u64 t, %1; cvt.u32.u64 %0, t; }" : "=r"(a) : "l"(p));
    return a;
}
static __device__ __forceinline__ void cpa16(uint32_t s, const void* g) {
    asm volatile("cp.async.cg.shared.global [%0], [%1], 16;" :: "r"(s), "l"(g));
}
static __device__ __forceinline__ void ldsm4(uint32_t& r0, uint32_t& r1,
                                             uint32_t& r2, uint32_t& r3, uint32_t addr) {
    asm volatile("ldmatrix.sync.aligned.m8n8.x4.shared.b16 {%0,%1,%2,%3}, [%4];"
                 : "=r"(r0), "=r"(r1), "=r"(r2), "=r"(r3) : "r"(addr));
}
static __device__ __forceinline__ void mma_f16(float* c, const uint32_t* a,
                                               uint32_t b0, uint32_t b1) {
    asm volatile(
        "mma.sync.aligned.m16n8k16.row.col.f32.f16.f16.f32 "
        "{%0,%1,%2,%3}, {%4,%5,%6,%7}, {%8,%9}, {%0,%1,%2,%3};"
        : "+f"(c[0]), "+f"(c[1]), "+f"(c[2]), "+f"(c[3])
        : "r"(a[0]), "r"(a[1]), "r"(a[2]), "r"(a[3]), "r"(b0), "r"(b1));
}
static __device__ __forceinline__ uint32_t sw128(uint32_t off) {
    return off ^ ((off >> 3) & 0x70);
}
// fast silu via explicit intrinsics: 1 EX2 + 1 RCP
static __device__ __forceinline__ float fsilu(float g) {
    return __fdividef(g, 1.f + __expf(-g));
}

// ---------------- RMSNorm (fp32 in, fp16-RNE out) ----------------
__global__ __launch_bounds__(256) void rmsnorm_kernel(
    const float* __restrict__ x, const float* __restrict__ w, __half* __restrict__ out)
{
    long row = blockIdx.x;
    const float4* xr = (const float4*)(x + row * (long)HID);
    const float4* wr = (const float4*)w;
    __half2* orow = (__half2*)(out + row * (long)HID);
    int tid = threadIdx.x;

    float4 v0 = xr[tid];
    float4 v1 = xr[tid + 256];
    float ss = v0.x*v0.x + v0.y*v0.y + v0.z*v0.z + v0.w*v0.w
             + v1.x*v1.x + v1.y*v1.y + v1.z*v1.z + v1.w*v1.w;

    #pragma unroll
    for (int off = 16; off > 0; off >>= 1)
        ss += __shfl_xor_sync(0xffffffffu, ss, off);

    __shared__ float warp_ss[8];
    __shared__ float s_scale;
    int lane = tid & 31, wid = tid >> 5;
    if (lane == 0) warp_ss[wid] = ss;
    __syncthreads();
    if (tid == 0) {
        float tot = 0.f;
        #pragma unroll
        for (int i = 0; i < 8; i++) tot += warp_ss[i];
        s_scale = rsqrtf(tot / (float)HID + EPS);
    }
    __syncthreads();
    float scale = s_scale;

    float4 w0 = wr[tid];
    float4 w1 = wr[tid + 256];
    orow[2*tid]       = __floats2half2_rn(v0.x * scale * w0.x, v0.y * scale * w0.y);
    orow[2*tid + 1]   = __floats2half2_rn(v0.z * scale * w0.z, v0.w * scale * w0.w);
    orow[2*tid + 512] = __floats2half2_rn(v1.x * scale * w1.x, v1.y * scale * w1.y);
    orow[2*tid + 513] = __floats2half2_rn(v1.z * scale * w1.z, v1.w * scale * w1.w);
}

// ---------------- fp32 -> fp16(RNE) elementwise ----------------
__global__ __launch_bounds__(256) void to_f16_kernel(
    const float4* __restrict__ s, uint2* __restrict__ d, long n4)
{
    long i = (long)blockIdx.x * blockDim.x + threadIdx.x;
    long stride = (long)gridDim.x * blockDim.x;
    for (; i < n4; i += stride) {
        float4 v = s[i];
        __half2 lo = __floats2half2_rn(v.x, v.y);
        __half2 hi = __floats2half2_rn(v.z, v.w);
        uint2 o;
        o.x = *(uint32_t*)&lo;
        o.y = *(uint32_t*)&hi;
        d[i] = o;
    }
}

// ---------------- Wqo prep: Wq -> fp16 transposed, Wo -> fp16, one kernel ----------------
__global__ __launch_bounds__(256) void prep_wqo_kernel(
    const float* __restrict__ Wq, const float* __restrict__ Wo,
    __half* __restrict__ WqT, __half* __restrict__ WoH)
{
    __shared__ float tile[32][33];
    int x = blockIdx.x * 32 + threadIdx.x;   // src col
    int y0 = blockIdx.y * 32 + threadIdx.y;  // src row
    #pragma unroll
    for (int i = 0; i < 32; i += 8) {
        size_t idx = (size_t)(y0 + i) * HID + x;
        tile[threadIdx.y + i][threadIdx.x] = Wq[idx];
        WoH[idx] = __float2half_rn(Wo[idx]);   // straight convert, coalesced
    }
    __syncthreads();
    int tx = blockIdx.y * 32 + threadIdx.x;  // dst col (= src row)
    int ty = blockIdx.x * 32 + threadIdx.y;  // dst row (= src col)
    #pragma unroll
    for (int i = 0; i < 32; i += 8)
        WqT[(size_t)(ty + i) * HID + tx] = __float2half_rn(tile[threadIdx.x][threadIdx.y + i]);
}

// ---------------- combine: out = hidden + p0 + p1 + p2 + p3 ----------------
__global__ __launch_bounds__(256) void combine_kernel(
    const float4* __restrict__ h, const float4* __restrict__ p,
    float4* __restrict__ o, long n4)
{
    long i = (long)blockIdx.x * blockDim.x + threadIdx.x;
    long stride = (long)gridDim.x * blockDim.x;
    for (; i < n4; i += stride) {
        float4 a = h[i];
        float4 b0 = p[i];
        float4 b1 = p[i + n4];
        float4 b2 = p[i + 2*n4];
        float4 b3 = p[i + 3*n4];
        float4 v;
        v.x = a.x + b0.x + b1.x + b2.x + b3.x;
        v.y = a.y + b0.y + b1.y + b2.y + b3.y;
        v.z = a.z + b0.z + b1.z + b2.z + b3.z;
        v.w = a.w + b0.w + b1.w + b2.w + b3.w;
        o[i] = v;
    }
}

// ---------------- plain GEMM: C[M,N] = A @ W^T (+R), mma.sync fp16 ----------------
// CTA tile 128x256, BK=64, 4-slot/3-inflight cp.async, single sync per iter,
// 16 warps (4M x 4N), warp tile 32x64, kk-level fragment double buffering.
// EPI 0: C(half) = rn(A@W^T);  EPI 1: C(float) = R + A@W^T
template<int EPI>
__global__ __launch_bounds__(NTHREADS, 1) void gemm_mma(
    const __half* __restrict__ A, const __half* __restrict__ W,
    const float* __restrict__ R, void* __restrict__ Cv, int K, int N)
{
    extern __shared__ __align__(1024) char smem[];
    uint32_t sb = s2u(smem);
    int tid = threadIdx.x;
    int lane = tid & 31, w = tid >> 5;
    int wm = w >> 2;      // 0..3  (32-row slice)
    int wn = w & 3;       // 0..3  (64-col slice)
    size_t row0 = (size_t)blockIdx.x * 128;
    size_t col0 = (size_t)blockIdx.y * 256;
    const int NK = K / BK;

    const __half* Abase = A + row0 * (size_t)K;
    const __half* Wbase = W + col0 * (size_t)K;

    auto load_stage = [&](int slot, int j) {
        uint32_t ab = sb + (uint32_t)slot * STAGE_B;
        uint32_t bb = ab + 16384;
        int kt = j * BK;
        #pragma unroll
        for (int p = 0; p < 2; p++) {
            int idx = p * NTHREADS + tid;
            int r = idx >> 3, c = idx & 7;   // 8 x 16B chunks per 128B row
            cpa16(ab + sw128((r << 7) + (c << 4)),
                  (const char*)(Abase + (size_t)r * K + kt) + (c << 4));
        }
        #pragma unroll
        for (int p = 0; p < 4; p++) {
            int idx = p * NTHREADS + tid;
            int r = idx >> 3, c = idx & 7;
            cpa16(bb + sw128((r << 7) + (c << 4)),
                  (const char*)(Wbase + (size_t)r * K + kt) + (c << 4));
        }
    };

    auto load_afr = [&](uint32_t ab, int kk, uint32_t af[2][4]) {
        #pragma unroll
        for (int mi = 0; mi < 2; mi++) {
            uint32_t off = (uint32_t)((wm * 32 + mi * 16 + (lane & 15)) << 7)
                         + (uint32_t)((kk << 5) + ((lane >> 4) << 4));
            ldsm4(af[mi][0], af[mi][1], af[mi][2], af[mi][3], ab + sw128(off));
        }
    };
    auto load_bfr = [&](uint32_t bb, int kk, uint32_t bf[8][2]) {
        #pragma unroll
        for (int bi = 0; bi < 4; bi++) {
            uint32_t off = (uint32_t)((wn * 64 + bi * 16 + ((lane >> 4) << 3) + (lane & 7)) << 7)
                         + (uint32_t)((kk << 5) + (((lane >> 3) & 1) << 4));
            ldsm4(bf[2*bi][0], bf[2*bi][1], bf[2*bi+1][0], bf[2*bi+1][1], bb + sw128(off));
        }
    };

    float acc[2][8][4];
    #pragma unroll
    for (int i = 0; i < 2; i++)
        #pragma unroll
        for (int jx = 0; jx < 8; jx++)
            #pragma unroll
            for (int e = 0; e < 4; e++) acc[i][jx][e] = 0.f;

    #pragma unroll
    for (int p = 0; p < STAGES - 1; p++) {
        load_stage(p, p);
        asm volatile("cp.async.commit_group;");
    }

    for (int j = 0; j < NK; j++) {
        asm volatile("cp.async.wait_group %0;" :: "n"(STAGES - 2));
        __syncthreads();
        if (j + STAGES - 1 < NK) load_stage((j + STAGES - 1) & 3, j + STAGES - 1);
        asm volatile("cp.async.commit_group;");

        int slot = j & 3;
        uint32_t ab = sb + (uint32_t)slot * STAGE_B;
        uint32_t bb = ab + 16384;

        uint32_t afr[2][2][4], bfr[2][8][2];
        load_afr(ab, 0, afr[0]);
        load_bfr(bb, 0, bfr[0]);
        #pragma unroll
        for (int kk = 0; kk < 4; kk++) {
            if (kk < 3) {
                load_afr(ab, kk + 1, afr[(kk + 1) & 1]);
                load_bfr(bb, kk + 1, bfr[(kk + 1) & 1]);
            }
            #pragma unroll
            for (int mi = 0; mi < 2; mi++)
                #pragma unroll
                for (int nj = 0; nj < 8; nj++)
                    mma_f16(acc[mi][nj], afr[kk & 1][mi], bfr[kk & 1][nj][0], bfr[kk & 1][nj][1]);
        }
        __syncthreads();
    }

    #pragma unroll
    for (int mi = 0; mi < 2; mi++) {
        size_t r = row0 + wm * 32 + mi * 16 + (lane >> 2);
        #pragma unroll
        for (int nj = 0; nj < 8; nj++) {
            size_t c = col0 + wn * 64 + nj * 8 + 2 * (lane & 3);
            if (EPI == 1) {
                float* C = (float*)Cv;
                const float2 r0 = *(const float2*)(R + r * (size_t)N + c);
                const float2 r1 = *(const float2*)(R + (r + 8) * (size_t)N + c);
                float2 v0 = make_float2(acc[mi][nj][0] + r0.x, acc[mi][nj][1] + r0.y);
                float2 v1 = make_float2(acc[mi][nj][2] + r1.x, acc[mi][nj][3] + r1.y);
                *(float2*)(C + r * (size_t)N + c) = v0;
                *(float2*)(C + (r + 8) * (size_t)N + c) = v1;
            } else {
                __half2* C = (__half2*)Cv;
                C[(r * (size_t)N + c) >> 1]       = __floats2half2_rn(acc[mi][nj][0], acc[mi][nj][1]);
                C[((r + 8) * (size_t)N + c) >> 1] = __floats2half2_rn(acc[mi][nj][2], acc[mi][nj][3]);
            }
        }
    }
}

// ---------------- down-proj split-K GEMM: P[z] = A[:, Kz] @ Wd[:, Kz]^T ----------------
// Identical 128x256 mainloop; blockIdx.z selects K-chunk (43/43/43/42 BK-blocks).
// Writes fp32 partials; combine_kernel sums them with the residual.
__global__ __launch_bounds__(NTHREADS, 1) void gemm_down_sk(
    const __half* __restrict__ A, const __half* __restrict__ W,
    float* __restrict__ P, int K, int N)
{
    extern __shared__ __align__(1024) char smem[];
    uint32_t sb = s2u(smem);
    int tid = threadIdx.x;
    int lane = tid & 31, w = tid >> 5;
    int wm = w >> 2;
    int wn = w & 3;
    size_t row0 = (size_t)blockIdx.x * 128;
    size_t col0 = (size_t)blockIdx.y * 256;
    int z = blockIdx.z;
    int nk0 = z * NK_CHUNK;
    int NK = NKTOT_DOWN - nk0 < NK_CHUNK ? NKTOT_DOWN - nk0 : NK_CHUNK;

    const __half* Abase = A + row0 * (size_t)K + (size_t)nk0 * BK;
    const __half* Wbase = W + col0 * (size_t)K + (size_t)nk0 * BK;
    float* Pz = P + (size_t)z * T_TOK * HID;

    auto load_stage = [&](int slot, int j) {
        uint32_t ab = sb + (uint32_t)slot * STAGE_B;
        uint32_t bb = ab + 16384;
        int kt = j * BK;
        #pragma unroll
        for (int p = 0; p < 2; p++) {
            int idx = p * NTHREADS + tid;
            int r = idx >> 3, c = idx & 7;
            cpa16(ab + sw128((r << 7) + (c << 4)),
                  (const char*)(Abase + (size_t)r * K + kt) + (c << 4));
        }
        #pragma unroll
        for (int p = 0; p < 4; p++) {
            int idx = p * NTHREADS + tid;
            int r = idx >> 3, c = idx & 7;
            cpa16(bb + sw128((r << 7) + (c << 4)),
                  (const char*)(Wbase + (size_t)r * K + kt) + (c << 4));
        }
    };

    auto load_afr = [&](uint32_t ab, int kk, uint32_t af[2][4]) {
        #pragma unroll
        for (int mi = 0; mi < 2; mi++) {
            uint32_t off = (uint32_t)((wm * 32 + mi * 16 + (lane & 15)) << 7)
                         + (uint32_t)((kk << 5) + ((lane >> 4) << 4));
            ldsm4(af[mi][0], af[mi][1], af[mi][2], af[mi][3], ab + sw128(off));
        }
    };
    auto load_bfr = [&](uint32_t bb, int kk, uint32_t bf[8][2]) {
        #pragma unroll
        for (int bi = 0; bi < 4; bi++) {
            uint32_t off = (uint32_t)((wn * 64 + bi * 16 + ((lane >> 4) << 3) + (lane & 7)) << 7)
                         + (uint32_t)((kk << 5) + (((lane >> 3) & 1) << 4));
            ldsm4(bf[2*bi][0], bf[2*bi][1], bf[2*bi+1][0], bf[2*bi+1][1], bb + sw128(off));
        }
    };

    float acc[2][8][4];
    #pragma unroll
    for (int i = 0; i < 2; i++)
        #pragma unroll
        for (int jx = 0; jx < 8; jx++)
            #pragma unroll
            for (int e = 0; e < 4; e++) acc[i][jx][e] = 0.f;

    #pragma unroll
    for (int p = 0; p < STAGES - 1; p++) {
        load_stage(p, p);
        asm volatile("cp.async.commit_group;");
    }

    for (int j = 0; j < NK; j++) {
        asm volatile("cp.async.wait_group %0;" :: "n"(STAGES - 2));
        __syncthreads();
        if (j + STAGES - 1 < NK) load_stage((j + STAGES - 1) & 3, j + STAGES - 1);
        asm volatile("cp.async.commit_group;");

        int slot = j & 3;
        uint32_t ab = sb + (uint32_t)slot * STAGE_B;
        uint32_t bb = ab + 16384;

        uint32_t afr[2][2][4], bfr[2][8][2];
        load_afr(ab, 0, afr[0]);
        load_bfr(bb, 0, bfr[0]);
        #pragma unroll
        for (int kk = 0; kk < 4; kk++) {
            if (kk < 3) {
                load_afr(ab, kk + 1, afr[(kk + 1) & 1]);
                load_bfr(bb, kk + 1, bfr[(kk + 1) & 1]);
            }
            #pragma unroll
            for (int mi = 0; mi < 2; mi++)
                #pragma unroll
                for (int nj = 0; nj < 8; nj++)
                    mma_f16(acc[mi][nj], afr[kk & 1][mi], bfr[kk & 1][nj][0], bfr[kk & 1][nj][1]);
        }
        __syncthreads();
    }

    #pragma unroll
    for (int mi = 0; mi < 2; mi++) {
        size_t r = row0 + wm * 32 + mi * 16 + (lane >> 2);
        #pragma unroll
        for (int nj = 0; nj < 8; nj++) {
            size_t c = col0 + wn * 64 + nj * 8 + 2 * (lane & 3);
            *(float2*)(Pz + r * (size_t)N + c)       = make_float2(acc[mi][nj][0], acc[mi][nj][1]);
            *(float2*)(Pz + (r + 8) * (size_t)N + c) = make_float2(acc[mi][nj][2], acc[mi][nj][3]);
        }
    }
}

// ---------------- fused gate/up GEMM: act(half) = rn(silu(A@Wg^T) * (A@Wu^T)) ----------------
__global__ __launch_bounds__(NTHREADS, 1) void gemm_gateup_mma(
    const __half* __restrict__ A, const __half* __restrict__ Wg,
    const __half* __restrict__ Wu, __half* __restrict__ C, int K, int N)
{
    extern __shared__ __align__(1024) char smem[];
    uint32_t sb = s2u(smem);
    int tid = threadIdx.x;
    int lane = tid & 31, w = tid >> 5;
    int wm = w >> 2;      // 0..3 (32-row slice)
    int wn = w & 3;       // 0..3 (32-col slice)
    size_t row0 = (size_t)blockIdx.x * 128;
    size_t col0 = (size_t)blockIdx.y * 128;
    const int NK = K / BK;

    const __half* Abase = A + row0 * (size_t)K;
    const __half* Gbase = Wg + col0 * (size_t)K;
    const __half* Ubase = Wu + col0 * (size_t)K;
    int nvalid = (int)((size_t)N - col0 < 128 ? (size_t)N - col0 : 128);

    auto load_stage = [&](int slot, int j) {
        uint32_t ab = sb + (uint32_t)slot * STAGE_B;
        uint32_t gb = ab + 16384;
        uint32_t ub = gb + 16384;
        int kt = j * BK;
        #pragma unroll
        for (int p = 0; p < 2; p++) {
            int idx = p * NTHREADS + tid;
            int r = idx >> 3, c = idx & 7;
            cpa16(ab + sw128((r << 7) + (c << 4)),
                  (const char*)(Abase + (size_t)r * K + kt) + (c << 4));
        }
        #pragma unroll
        for (int p = 0; p < 2; p++) {
            int idx = p * NTHREADS + tid;
            int r = idx >> 3, c = idx & 7;
            if (r < nvalid) {
                uint32_t swo = sw128((r << 7) + (c << 4));
                cpa16(gb + swo, (const char*)(Gbase + (size_t)r * K + kt) + (c << 4));
                cpa16(ub + swo, (const char*)(Ubase + (size_t)r * K + kt) + (c << 4));
            }
        }
    };

    auto load_afr = [&](uint32_t ab, int kk, uint32_t af[2][4]) {
        #pragma unroll
        for (int mi = 0; mi < 2; mi++) {
            uint32_t off = (uint32_t)((wm * 32 + mi * 16 + (lane & 15)) << 7)
                         + (uint32_t)((kk << 5) + ((lane >> 4) << 4));
            ldsm4(af[mi][0], af[mi][1], af[mi][2], af[mi][3], ab + sw128(off));
        }
    };
    auto load_wfr = [&](uint32_t wb, int kk, uint32_t wf[4][2]) {
        #pragma unroll
        for (int bi = 0; bi < 2; bi++) {
            uint32_t off = (uint32_t)((wn * 32 + bi * 16 + ((lane >> 4) << 3) + (lane & 7)) << 7)
                         + (uint32_t)((kk << 5) + (((lane >> 3) & 1) << 4));
            ldsm4(wf[2*bi][0], wf[2*bi][1], wf[2*bi+1][0], wf[2*bi+1][1], wb + sw128(off));
        }
    };

    float accg[2][4][4], accu[2][4][4];
    #pragma unroll
    for (int i = 0; i < 2; i++)
        #pragma unroll
        for (int jx = 0; jx < 4; jx++)
            #pragma unroll
            for (int e = 0; e < 4; e++) { accg[i][jx][e] = 0.f; accu[i][jx][e] = 0.f; }

    #pragma unroll
    for (int p = 0; p < STAGES - 1; p++) {
        load_stage(p, p);
        asm volatile("cp.async.commit_group;");
    }

    for (int j = 0; j < NK; j++) {
        asm volatile("cp.async.wait_group %0;" :: "n"(STAGES - 2));
        __syncthreads();
        if (j + STAGES - 1 < NK) load_stage((j + STAGES - 1) & 3, j + STAGES - 1);
        asm volatile("cp.async.commit_group;");

        int slot = j & 3;
        uint32_t ab = sb + (uint32_t)slot * STAGE_B;
        uint32_t gb = ab + 16384;
        uint32_t ub = gb + 16384;

        uint32_t afr[2][2][4], gfr[2][4][2], ufr[2][4][2];
        load_afr(ab, 0, afr[0]);
        load_wfr(gb, 0, gfr[0]);
        load_wfr(ub, 0, ufr[0]);
        #pragma unroll
        for (int kk = 0; kk < 4; kk++) {
            if (kk < 3) {
                load_afr(ab, kk + 1, afr[(kk + 1) & 1]);
                load_wfr(gb, kk + 1, gfr[(kk + 1) & 1]);
                load_wfr(ub, kk + 1, ufr[(kk + 1) & 1]);
            }
            #pragma unroll
            for (int mi = 0; mi < 2; mi++)
                #pragma unroll
                for (int nj = 0; nj < 4; nj++) {
                    mma_f16(accg[mi][nj], afr[kk & 1][mi], gfr[kk & 1][nj][0], gfr[kk & 1][nj][1]);
                    mma_f16(accu[mi][nj], afr[kk & 1][mi], ufr[kk & 1][nj][0], ufr[kk & 1][nj][1]);
                }
        }
        __syncthreads();
    }

    #pragma unroll
    for (int mi = 0; mi < 2; mi++) {
        size_t r = row0 + wm * 32 + mi * 16 + (lane >> 2);
        #pragma unroll
        for (int nj = 0; nj < 4; nj++) {
            size_t c = col0 + wn * 32 + nj * 8 + 2 * (lane & 3);
            if (c < (size_t)N) {
                __half2 v0 = __floats2half2_rn(fsilu(accg[mi][nj][0]) * accu[mi][nj][0],
                                               fsilu(accg[mi][nj][1]) * accu[mi][nj][1]);
                __half2 v1 = __floats2half2_rn(fsilu(accg[mi][nj][2]) * accu[mi][nj][2],
                                               fsilu(accg[mi][nj][3]) * accu[mi][nj][3]);
                *(__half2*)(C + r * (size_t)N + c) = v0;
                *(__half2*)(C + (r + 8) * (size_t)N + c) = v1;
            }
        }
    }
}

// ---------------- launch ----------------
extern "C" void kernel_launch(void* const* d_in, const int* in_sizes, int n_in,
                              void* d_out, int out_size)
{
    const float* x      = (const float*)d_in[0];
    const float* in_w   = (const float*)d_in[2];
    const float* post_w = (const float*)d_in[3];
    const float* Wq     = (const float*)d_in[4];
    const float* Wo     = (const float*)d_in[5];
    const float* Wg     = (const float*)d_in[6];
    const float* Wu     = (const float*)d_in[7];
    const float* Wd     = (const float*)d_in[8];
    float* out = (float*)d_out;

    __half *hnorm, *hpost, *act, *hWqT, *hWo, *hWqo, *hWg, *hWu, *hWd;
    float *hidden, *part;
    cudaGetSymbolAddress((void**)&hnorm,  g_hnorm);
    cudaGetSymbolAddress((void**)&hidden, g_hidden);
    cudaGetSymbolAddress((void**)&hpost,  g_hpost);
    cudaGetSymbolAddress((void**)&act,    g_act);
    cudaGetSymbolAddress((void**)&part,   g_part);
    cudaGetSymbolAddress((void**)&hWqT,   g_hWqT);
    cudaGetSymbolAddress((void**)&hWo,    g_hWo);
    cudaGetSymbolAddress((void**)&hWqo,   g_hWqo);
    cudaGetSymbolAddress((void**)&hWg,    g_hWg);
    cudaGetSymbolAddress((void**)&hWu,    g_hWu);
    cudaGetSymbolAddress((void**)&hWd,    g_hWd);

    static cudaStream_t s2 = nullptr;
    static cudaEvent_t ev_fork = nullptr, ev_wqo = nullptr, ev_join = nullptr;
    if (s2 == nullptr) {
        cudaStreamCreateWithFlags(&s2, cudaStreamNonBlocking);
        cudaEventCreateWithFlags(&ev_fork, cudaEventDisableTiming);
        cudaEventCreateWithFlags(&ev_wqo,  cudaEventDisableTiming);
        cudaEventCreateWithFlags(&ev_join, cudaEventDisableTiming);
        cudaFuncSetAttribute(gemm_mma<0>, cudaFuncAttributeMaxDynamicSharedMemorySize, SMEM_TOTAL);
        cudaFuncSetAttribute(gemm_mma<1>, cudaFuncAttributeMaxDynamicSharedMemorySize, SMEM_TOTAL);
        cudaFuncSetAttribute(gemm_down_sk, cudaFuncAttributeMaxDynamicSharedMemorySize, SMEM_TOTAL);
        cudaFuncSetAttribute(gemm_gateup_mma, cudaFuncAttributeMaxDynamicSharedMemorySize, SMEM_TOTAL);
    }

    const int CB = 1184;

    // ---- fork: Wqo chain first on s2 (it heads the critical path), then big converts ----
    cudaEventRecord(ev_fork, 0);
    cudaStreamWaitEvent(s2, ev_fork, 0);
    // Wq -> fp16 transposed AND Wo -> fp16, single kernel
    prep_wqo_kernel<<<dim3(HID/32, HID/32), dim3(32, 8), 0, s2>>>(Wq, Wo, hWqT, hWo);
    // Wqo = rn16(Wo @ Wq):  C[i,j] = sum_q Wo[i,q] * WqT[j,q]
    gemm_mma<0><<<dim3(HID/128, HID/256), NTHREADS, SMEM_TOTAL, s2>>>(hWo, hWqT, nullptr, hWqo, HID, HID);
    cudaEventRecord(ev_wqo, s2);
    // big MLP weight converts (overlap the hidden GEMM on the main stream)
    to_f16_kernel<<<CB, 256, 0, s2>>>((const float4*)Wg, (uint2*)hWg, (long)INTERD * HID / 4);
    to_f16_kernel<<<CB, 256, 0, s2>>>((const float4*)Wu, (uint2*)hWu, (long)INTERD * HID / 4);
    to_f16_kernel<<<CB, 256, 0, s2>>>((const float4*)Wd, (uint2*)hWd, (long)HID * INTERD / 4);
    cudaEventRecord(ev_join, s2);

    // ---- main stream ----
    // 1. h_norm = rn(rmsnorm(x) * in_w)   (concurrent with the Wqo chain)
    rmsnorm_kernel<<<T_TOK, 256>>>(x, in_w, hnorm);
    cudaStreamWaitEvent(0, ev_wqo, 0);
    // 2+3 fused. hidden = x + h_norm @ Wqo^T
    gemm_mma<1><<<dim3(T_TOK/128, HID/256), NTHREADS, SMEM_TOTAL>>>(hnorm, hWqo, x, hidden, HID, HID);
    // 4. h_post = rn(rmsnorm(hidden) * post_w)
    rmsnorm_kernel<<<T_TOK, 256>>>(hidden, post_w, hpost);
    // join: MLP weight converts must be done
    cudaStreamWaitEvent(0, ev_join, 0);
    // 5. act = rn(silu(h_post @ Wg^T) * (h_post @ Wu^T))   [86 tiles, last ragged 64]
    gemm_gateup_mma<<<dim3(T_TOK/128, (INTERD + 127)/128), NTHREADS, SMEM_TOTAL>>>(hpost, hWg, hWu, act, HID, INTERD);
    // 6. split-K down: P[z] = act[:, Kz] @ Wd[:, Kz]^T  (grid z = 4 chunks, 1024 CTAs)
    gemm_down_sk<<<dim3(T_TOK/128, HID/256, 4), NTHREADS, SMEM_TOTAL>>>(act, hWd, part, INTERD, HID);
    // 7. out = hidden + p0 + p1 + p2 + p3
    combine_kernel<<<CB, 256>>>((const float4*)hidden, (const float4*)part, (float4*)out,
                                (long)T_TOK * HID / 4);
}